// round 10
// baseline (speedup 1.0000x reference)
#include <cuda_runtime.h>
#include <cuda_fp16.h>
#include <math.h>
#include <stdint.h>

// ---------------------------------------------------------------------------
// Problem constants
// ---------------------------------------------------------------------------
#define BB       256
#define DIM      32768
#define KB       64                 // k-block (fp16 cols per smem stage) = 128 B/row
#define NKB_TOT  (DIM / KB)         // 512 k-blocks per tile
#define NTILE    3                  // (0,0), (0,1), (1,1) -- (1,0) by symmetry
#define NWORK    (NTILE * NKB_TOT)  // 1536 work items
#define NCTA     128
#define WPC      (NWORK / NCTA)     // 12 k-blocks per CTA
#define STRIDE   144                // smem row stride (128 B data + 16 B pad)
#define TILE_SM  (128 * STRIDE)
#define STAGE    (2 * TILE_SM)
#define NSTAGE   3
#define SMEM_TOTAL (NSTAGE * STAGE) // 110592 B
#define MARGIN   0.003f
#define TILE_ELEMS 16384            // 128*128 floats per partial slot

// ---------------------------------------------------------------------------
// Static device scratch (no allocations anywhere)
// ---------------------------------------------------------------------------
__device__ __align__(16) __half g_h[BB * DIM];       // 16 MB fp16 copy of X
__device__ float  g_part[2 * NCTA * TILE_ELEMS];     // 16 MB: 256 tagged slots
__device__ int    g_tag[2 * NCTA];
__device__ float  g_G[BB * BB];
__device__ float  g_sq[BB];
__device__ double g_lossp[BB];
__device__ double g_cntp[BB];
__device__ int    g_count;

// ---------------------------------------------------------------------------
// Helpers
// ---------------------------------------------------------------------------
__device__ __forceinline__ uint32_t smem_u32(const void* p) {
    uint32_t a;
    asm("{ .reg .u64 t; cvta.to.shared.u64 t, %1; cvt.u32.u64 %0, t; }" : "=r"(a) : "l"(p));
    return a;
}
__device__ __forceinline__ void cpasync16(uint32_t s, const void* g) {
    asm volatile("cp.async.cg.shared.global [%0], [%1], 16;" :: "r"(s), "l"(g) : "memory");
}
__device__ __forceinline__ void ldm_x4(uint32_t a, uint32_t& r0, uint32_t& r1,
                                       uint32_t& r2, uint32_t& r3) {
    asm volatile("ldmatrix.sync.aligned.m8n8.x4.shared.b16 {%0,%1,%2,%3}, [%4];"
                 : "=r"(r0), "=r"(r1), "=r"(r2), "=r"(r3) : "r"(a));
}
__device__ __forceinline__ void mma16816(float& c0, float& c1, float& c2, float& c3,
                                         uint32_t a0, uint32_t a1, uint32_t a2, uint32_t a3,
                                         uint32_t b0, uint32_t b1) {
    asm volatile(
        "mma.sync.aligned.m16n8k16.row.col.f32.f16.f16.f32 "
        "{%0,%1,%2,%3}, {%4,%5,%6,%7}, {%8,%9}, {%0,%1,%2,%3};"
        : "+f"(c0), "+f"(c1), "+f"(c2), "+f"(c3)
        : "r"(a0), "r"(a1), "r"(a2), "r"(a3), "r"(b0), "r"(b1));
}

// ---------------------------------------------------------------------------
// Kernel 1: fp32 -> fp16 convert
// ---------------------------------------------------------------------------
__global__ __launch_bounds__(256) void convert_kernel(const float* __restrict__ X) {
    const int gid = blockIdx.x * 256 + threadIdx.x;
    const float4* s = reinterpret_cast<const float4*>(X) + (size_t)gid * 2;
    const float4 a = s[0];
    const float4 b = s[1];
    __half2 h0 = __floats2half2_rn(a.x, a.y);
    __half2 h1 = __floats2half2_rn(a.z, a.w);
    __half2 h2 = __floats2half2_rn(b.x, b.y);
    __half2 h3 = __floats2half2_rn(b.z, b.w);
    uint4 v;
    v.x = *reinterpret_cast<uint32_t*>(&h0);
    v.y = *reinterpret_cast<uint32_t*>(&h1);
    v.z = *reinterpret_cast<uint32_t*>(&h2);
    v.w = *reinterpret_cast<uint32_t*>(&h3);
    reinterpret_cast<uint4*>(g_h)[gid] = v;
}

// ---------------------------------------------------------------------------
// Kernel 2: symmetry-pruned split-K fp16 GEMM.
// Work item g in [0,1536): tile = g>>9 (0:(0,0) 1:(0,1) 2:(1,1)), kb = g&511.
// CTA c handles g in [12c, 12c+12); straddling CTAs flush mid-stream into a
// second tagged slot. RACE-FREE pipeline: prefetch issue happens AFTER the
// barrier, so writes to stage s can never overlap the previous reads of s.
// ---------------------------------------------------------------------------
extern __shared__ unsigned char dsm[];

__global__ __launch_bounds__(256, 1) void gemm_kernel() {
    const int bid  = blockIdx.x;
    const int t    = threadIdx.x;
    const int w    = t >> 5;
    const int lane = t & 31;
    const int wm   = w >> 2;
    const int wn   = w & 3;
    const uint32_t sb = smem_u32(dsm);

    float acc[4][4][4];
#pragma unroll
    for (int i = 0; i < 4; i++)
#pragma unroll
        for (int j = 0; j < 4; j++)
#pragma unroll
            for (int r = 0; r < 4; r++) acc[i][j][r] = 0.f;

    auto issue = [&](int g, int st_idx) {
        const int tile  = g >> 9;
        const int kcol  = (g & 511) * KB;
        const int arow0 = (tile == 2) ? 128 : 0;
        const int brow0 = (tile >= 1) ? 128 : 0;
        const uint32_t st = sb + st_idx * STAGE;
#pragma unroll
        for (int i = 0; i < 8; i++) {
            const int idx = t + 256 * i;
            const int ab  = idx >> 10;       // 0 = A, 1 = B
            const int s2  = idx & 1023;
            const int row = s2 >> 3;
            const int c   = s2 & 7;
            const __half* gp = g_h + (size_t)((ab ? brow0 : arow0) + row) * DIM + kcol + c * 8;
            cpasync16(st + ab * TILE_SM + row * STRIDE + c * 16, gp);
        }
        asm volatile("cp.async.commit_group;" ::: "memory");
    };

    const int rbase = wm * 64 + (lane >> 2);
    const int cbase = wn * 32 + (lane & 3) * 2;
    auto flushacc = [&](int slot) {
        float* out = g_part + (size_t)slot * TILE_ELEMS;
#pragma unroll
        for (int i = 0; i < 4; i++)
#pragma unroll
            for (int j = 0; j < 4; j++) {
                const int r0 = rbase + i * 16;
                const int c  = cbase + j * 8;
                *reinterpret_cast<float2*>(out + r0 * 128 + c)       = make_float2(acc[i][j][0], acc[i][j][1]);
                *reinterpret_cast<float2*>(out + (r0 + 8) * 128 + c) = make_float2(acc[i][j][2], acc[i][j][3]);
#pragma unroll
                for (int r = 0; r < 4; r++) acc[i][j][r] = 0.f;
            }
    };

    const int g0 = bid * WPC;
    issue(g0, 0);
    issue(g0 + 1, 1);

    const uint32_t a_ld = (uint32_t)(wm * 64 + (lane & 15)) * STRIDE + ((lane >> 4) & 1) * 16;
    const int bsel  = (lane >> 3) & 3;
    const uint32_t b_ld = (uint32_t)(wn * 32 + ((bsel >> 1) * 8) + (lane & 7)) * STRIDE
                        + (bsel & 1) * 16;

    int cur_tile = g0 >> 9;
    int seg = 0;
    for (int ii = 0; ii < WPC; ii++) {
        const int g = g0 + ii;
        const int st_idx = ii % NSTAGE;

        // Drain the group for stage st_idx (2 groups max in flight).
        if (ii + 1 < WPC) {
            asm volatile("cp.async.wait_group 1;" ::: "memory");
        } else {
            asm volatile("cp.async.wait_group 0;" ::: "memory");
        }
        __syncthreads();   // all threads done reading stage (ii-1) AND stage st_idx ready

        // Safe now: stage (ii+2)%3's last readers were iteration ii-1, retired above.
        if (ii + 2 < WPC) issue(g0 + ii + 2, (ii + 2) % NSTAGE);

        if ((g >> 9) != cur_tile) {          // tile boundary: flush segment 0
            flushacc(2 * bid);
            if (t == 0) g_tag[2 * bid] = cur_tile;
            cur_tile = g >> 9;
            seg = 1;
        }

        const uint32_t st = sb + st_idx * STAGE;
#pragma unroll
        for (int ks = 0; ks < 4; ks++) {
            const uint32_t ko = ks * 32;
            uint32_t af[4][4];
#pragma unroll
            for (int i = 0; i < 4; i++)
                ldm_x4(st + a_ld + (uint32_t)i * 16 * STRIDE + ko,
                       af[i][0], af[i][1], af[i][2], af[i][3]);
            uint32_t bf[2][4];
#pragma unroll
            for (int p = 0; p < 2; p++)
                ldm_x4(st + TILE_SM + b_ld + (uint32_t)p * 16 * STRIDE + ko,
                       bf[p][0], bf[p][1], bf[p][2], bf[p][3]);
#pragma unroll
            for (int i = 0; i < 4; i++)
#pragma unroll
                for (int j = 0; j < 4; j++) {
                    const int p = j >> 1, h = (j & 1) * 2;
                    mma16816(acc[i][j][0], acc[i][j][1], acc[i][j][2], acc[i][j][3],
                             af[i][0], af[i][1], af[i][2], af[i][3],
                             bf[p][h], bf[p][h + 1]);
                }
        }
    }

    flushacc(2 * bid + seg);
    if (t == 0) {
        g_tag[2 * bid + seg] = cur_tile;
        if (seg == 0) g_tag[2 * bid + 1] = -1;
    }
}

// ---------------------------------------------------------------------------
// Kernel 3: assemble G from tagged partial slots (deterministic ordered sum).
// Quadrants: (lo,lo)<-tile0, (lo,hi)<-tile1, (hi,hi)<-tile2,
// (hi,lo)<-tile1 transposed (coalesced load + smem transpose).
// Extracts diag -> g_sq; resets g_count.
// ---------------------------------------------------------------------------
__global__ __launch_bounds__(256) void reduce_kernel() {
    const int bi = blockIdx.x >> 3;
    const int bj = blockIdx.x & 7;
    const int t  = threadIdx.x;
    const int r  = t >> 3;
    const int c4 = (t & 7) * 4;

    __shared__ int tg[2 * NCTA];
    tg[t] = g_tag[t];
    __syncthreads();

    const int qi = bi >> 2, qj = bj >> 2;
    const int twant = (qi == 0) ? ((qj == 0) ? 0 : 1) : ((qj == 1) ? 2 : 1);
    const bool trans = (qi == 1 && qj == 0);

    int sr, sc;
    if (!trans) { sr = (bi & 3) * 32 + r; sc = (bj & 3) * 32 + c4; }
    else        { sr = (bj & 3) * 32 + r; sc = (bi & 3) * 32 + c4; }

    float4 acc = make_float4(0.f, 0.f, 0.f, 0.f);
#pragma unroll 1
    for (int slot = 0; slot < 2 * NCTA; slot++) {
        if (tg[slot] == twant) {
            float4 v = *reinterpret_cast<const float4*>(
                g_part + (size_t)slot * TILE_ELEMS + sr * 128 + sc);
            acc.x += v.x; acc.y += v.y; acc.z += v.z; acc.w += v.w;
        }
    }

    float4 gv;
    __shared__ float s2[32][33];
    if (!trans) {
        gv = acc;
    } else {
        s2[r][c4 + 0] = acc.x; s2[r][c4 + 1] = acc.y;
        s2[r][c4 + 2] = acc.z; s2[r][c4 + 3] = acc.w;
        __syncthreads();
        gv.x = s2[c4 + 0][r]; gv.y = s2[c4 + 1][r];
        gv.z = s2[c4 + 2][r]; gv.w = s2[c4 + 3][r];
    }

    const int grow = bi * 32 + r;
    const int gcol = bj * 32 + c4;
    *reinterpret_cast<float4*>(g_G + grow * BB + gcol) = gv;

    if (grow >= gcol && grow < gcol + 4) {   // diag element lives in this unit
        const int d = grow - gcol;
        g_sq[grow] = (d == 0) ? gv.x : (d == 1) ? gv.y : (d == 2) ? gv.z : gv.w;
    }
    if (blockIdx.x == 0 && t == 0) g_count = 0;
}

// ---------------------------------------------------------------------------
// Kernel 4: loss, warp-per-anchor (32 blocks x 8 warps = 256 anchors).
// loss(a) = sum_{k imp} sum_{b pos} relu((D_ab+m) - D_ak); cnt = nPos*nImp.
// Warp-local ballots/compaction; per-warp smem positives row padded with
// -1e30 (relu self-masks). Fused final reduction via last-block election.
// ---------------------------------------------------------------------------
__global__ __launch_bounds__(256) void loss_kernel(const int* __restrict__ mods,
                                                   float* __restrict__ out) {
    const int t    = threadIdx.x;
    const int w    = t >> 5;
    const int lane = t & 31;
    const int a    = blockIdx.x * 8 + w;

    __shared__ float pvw[8][BB + 8];
    __shared__ int   is_last;

    const int   ma  = mods[a];
    const float sqa = g_sq[a];

    float dak[8];
    float dvv[8];
    bool  pos[8], impb[8];
#pragma unroll
    for (int i = 0; i < 8; i++) {
        const int tt = i * 32 + lane;
        const int m  = mods[tt];
        const float sq = g_sq[tt];
        const float gg = g_G[a * BB + tt];
        float d2 = fmaxf(sqa + sq - 2.f * gg, 0.f);
        const float dv = (d2 > 0.f) ? sqrtf(d2) : 0.f;
        dvv[i]  = dv;
        impb[i] = (m != ma);
        pos[i]  = (!impb[i]) && (tt != a);
        dak[i]  = impb[i] ? dv : 1e30f;
    }

    const uint32_t lmask = (1u << lane) - 1u;
    int base = 0, nImp = 0;
#pragma unroll
    for (int i = 0; i < 8; i++) {
        const uint32_t bp = __ballot_sync(0xFFFFFFFFu, pos[i]);
        nImp += __popc(__ballot_sync(0xFFFFFFFFu, impb[i]));
        if (pos[i]) pvw[w][base + __popc(bp & lmask)] = dvv[i] + MARGIN;
        base += __popc(bp);
    }
    const int nPos = base;
    if (lane < 8) pvw[w][nPos + lane] = -1e30f;
    __syncwarp();

    float a0 = 0.f, a1 = 0.f;
    const int n4 = (nPos + 3) & ~3;
#pragma unroll 1
    for (int j = 0; j < n4; j += 4) {
#pragma unroll
        for (int jj = 0; jj < 4; jj++) {
            const float pv = pvw[w][j + jj];
#pragma unroll
            for (int i = 0; i < 8; i += 2) {
                a0 += fmaxf(pv - dak[i], 0.f);
                a1 += fmaxf(pv - dak[i + 1], 0.f);
            }
        }
    }
    float s = a0 + a1;
#pragma unroll
    for (int o = 16; o > 0; o >>= 1) s += __shfl_xor_sync(0xFFFFFFFFu, s, o);
    if (lane == 0) {
        g_lossp[a] = (double)s;
        g_cntp[a]  = (double)nPos * (double)nImp;
    }

    __syncthreads();
    __threadfence();
    if (t == 0) {
        int old = atomicAdd(&g_count, 1);
        is_last = (old == 31);
    }
    __syncthreads();
    if (is_last) {
        __threadfence();
        __shared__ double sL[BB], sC[BB];
        sL[t] = g_lossp[t];
        sC[t] = g_cntp[t];
        __syncthreads();
        for (int stride = 128; stride > 0; stride >>= 1) {
            if (t < stride) { sL[t] += sL[t + stride]; sC[t] += sC[t + stride]; }
            __syncthreads();
        }
        if (t == 0) out[0] = (float)(sL[0] / sC[0]);
    }
}

// ---------------------------------------------------------------------------
extern "C" void kernel_launch(void* const* d_in, const int* in_sizes, int n_in,
                              void* d_out, int out_size) {
    const float* X    = (const float*)d_in[0];
    const int*   mods = (const int*)  d_in[1];
    (void)in_sizes; (void)n_in; (void)out_size;

    cudaFuncSetAttribute(gemm_kernel, cudaFuncAttributeMaxDynamicSharedMemorySize, SMEM_TOTAL);

    convert_kernel<<<(BB * DIM / 8) / 256, 256>>>(X);
    gemm_kernel<<<NCTA, 256, SMEM_TOTAL>>>();
    reduce_kernel<<<64, 256>>>();
    loss_kernel<<<32, 256>>>(mods, (float*)d_out);
}

// round 11
// speedup vs baseline: 1.5551x; 1.5551x over previous
#include <cuda_runtime.h>
#include <cuda_fp16.h>
#include <math.h>
#include <stdint.h>

// ---------------------------------------------------------------------------
// Problem constants
// ---------------------------------------------------------------------------
#define BB       256
#define DIM      32768
#define KB       64                 // k-block (fp16 cols per smem stage) = 128 B/row
#define NKB_TOT  (DIM / KB)         // 512 k-blocks per tile
#define NTILE    3                  // (0,0), (0,1), (1,1) -- (1,0) by symmetry
#define NWORK    (NTILE * NKB_TOT)  // 1536 work items
#define NCTA     128
#define WPC      (NWORK / NCTA)     // 12 k-blocks per CTA
#define STRIDE   144                // smem row stride (128 B data + 16 B pad)
#define TILE_SM  (128 * STRIDE)
#define STAGE    (2 * TILE_SM)
#define NSTAGE   3
#define SMEM_TOTAL (NSTAGE * STAGE) // 110592 B
#define MARGIN   0.003f
#define TILE_ELEMS 16384            // 128*128 floats per partial slot
#define NSLOT    130                // 43 + 44 + 43 (static slot regions per tile)

// ---------------------------------------------------------------------------
// Static device scratch (no allocations anywhere)
// ---------------------------------------------------------------------------
__device__ __align__(16) __half g_h[BB * DIM];       // 16 MB fp16 copy of X
__device__ float  g_part[NSLOT * TILE_ELEMS];        // 8.5 MB partial slots
__device__ float  g_G[BB * BB];
__device__ float  g_sq[BB];
__device__ double g_lossp[BB];
__device__ double g_cntp[BB];
__device__ int    g_count;

// ---------------------------------------------------------------------------
// Helpers
// ---------------------------------------------------------------------------
__device__ __forceinline__ uint32_t smem_u32(const void* p) {
    uint32_t a;
    asm("{ .reg .u64 t; cvta.to.shared.u64 t, %1; cvt.u32.u64 %0, t; }" : "=r"(a) : "l"(p));
    return a;
}
__device__ __forceinline__ void cpasync16(uint32_t s, const void* g) {
    asm volatile("cp.async.cg.shared.global [%0], [%1], 16;" :: "r"(s), "l"(g) : "memory");
}
__device__ __forceinline__ void ldm_x4(uint32_t a, uint32_t& r0, uint32_t& r1,
                                       uint32_t& r2, uint32_t& r3) {
    asm volatile("ldmatrix.sync.aligned.m8n8.x4.shared.b16 {%0,%1,%2,%3}, [%4];"
                 : "=r"(r0), "=r"(r1), "=r"(r2), "=r"(r3) : "r"(a));
}
__device__ __forceinline__ void mma16816(float& c0, float& c1, float& c2, float& c3,
                                         uint32_t a0, uint32_t a1, uint32_t a2, uint32_t a3,
                                         uint32_t b0, uint32_t b1) {
    asm volatile(
        "mma.sync.aligned.m16n8k16.row.col.f32.f16.f16.f32 "
        "{%0,%1,%2,%3}, {%4,%5,%6,%7}, {%8,%9}, {%0,%1,%2,%3};"
        : "+f"(c0), "+f"(c1), "+f"(c2), "+f"(c3)
        : "r"(a0), "r"(a1), "r"(a2), "r"(a3), "r"(b0), "r"(b1));
}
// Static slot index: tile0 region [0,43), tile1 [43,87), tile2 [87,130)
__device__ __forceinline__ int slotof(int c, int tile) {
    return (tile == 0) ? c : (tile == 1) ? 43 + (c - 42) : 87 + (c - 85);
}

// ---------------------------------------------------------------------------
// Kernel 1: fp32 -> fp16 convert
// ---------------------------------------------------------------------------
__global__ __launch_bounds__(256) void convert_kernel(const float* __restrict__ X) {
    const int gid = blockIdx.x * 256 + threadIdx.x;
    const float4* s = reinterpret_cast<const float4*>(X) + (size_t)gid * 2;
    const float4 a = s[0];
    const float4 b = s[1];
    __half2 h0 = __floats2half2_rn(a.x, a.y);
    __half2 h1 = __floats2half2_rn(a.z, a.w);
    __half2 h2 = __floats2half2_rn(b.x, b.y);
    __half2 h3 = __floats2half2_rn(b.z, b.w);
    uint4 v;
    v.x = *reinterpret_cast<uint32_t*>(&h0);
    v.y = *reinterpret_cast<uint32_t*>(&h1);
    v.z = *reinterpret_cast<uint32_t*>(&h2);
    v.w = *reinterpret_cast<uint32_t*>(&h3);
    reinterpret_cast<uint4*>(g_h)[gid] = v;
}

// ---------------------------------------------------------------------------
// Kernel 2: symmetry-pruned split-K fp16 GEMM (validated in R10).
// Work item g in [0,1536): tile = g>>9 (0:(0,0) 1:(0,1) 2:(1,1)), kb = g&511.
// CTA c handles [12c, 12c+12); straddlers (c=42, c=85) flush mid-stream.
// Slots are STATIC per (CTA, tile) -- no tags. Race-free prefetch ordering.
// ---------------------------------------------------------------------------
extern __shared__ unsigned char dsm[];

__global__ __launch_bounds__(256, 1) void gemm_kernel() {
    const int bid  = blockIdx.x;
    const int t    = threadIdx.x;
    const int w    = t >> 5;
    const int lane = t & 31;
    const int wm   = w >> 2;
    const int wn   = w & 3;
    const uint32_t sb = smem_u32(dsm);

    float acc[4][4][4];
#pragma unroll
    for (int i = 0; i < 4; i++)
#pragma unroll
        for (int j = 0; j < 4; j++)
#pragma unroll
            for (int r = 0; r < 4; r++) acc[i][j][r] = 0.f;

    auto issue = [&](int g, int st_idx) {
        const int tile  = g >> 9;
        const int kcol  = (g & 511) * KB;
        const int arow0 = (tile == 2) ? 128 : 0;
        const int brow0 = (tile >= 1) ? 128 : 0;
        const uint32_t st = sb + st_idx * STAGE;
#pragma unroll
        for (int i = 0; i < 8; i++) {
            const int idx = t + 256 * i;
            const int ab  = idx >> 10;       // 0 = A, 1 = B
            const int s2  = idx & 1023;
            const int row = s2 >> 3;
            const int c   = s2 & 7;
            const __half* gp = g_h + (size_t)((ab ? brow0 : arow0) + row) * DIM + kcol + c * 8;
            cpasync16(st + ab * TILE_SM + row * STRIDE + c * 16, gp);
        }
        asm volatile("cp.async.commit_group;" ::: "memory");
    };

    const int rbase = wm * 64 + (lane >> 2);
    const int cbase = wn * 32 + (lane & 3) * 2;
    auto flushacc = [&](int slot) {
        float* out = g_part + (size_t)slot * TILE_ELEMS;
#pragma unroll
        for (int i = 0; i < 4; i++)
#pragma unroll
            for (int j = 0; j < 4; j++) {
                const int r0 = rbase + i * 16;
                const int c  = cbase + j * 8;
                *reinterpret_cast<float2*>(out + r0 * 128 + c)       = make_float2(acc[i][j][0], acc[i][j][1]);
                *reinterpret_cast<float2*>(out + (r0 + 8) * 128 + c) = make_float2(acc[i][j][2], acc[i][j][3]);
#pragma unroll
                for (int r = 0; r < 4; r++) acc[i][j][r] = 0.f;
            }
    };

    const int g0 = bid * WPC;
    issue(g0, 0);
    issue(g0 + 1, 1);

    const uint32_t a_ld = (uint32_t)(wm * 64 + (lane & 15)) * STRIDE + ((lane >> 4) & 1) * 16;
    const int bsel  = (lane >> 3) & 3;
    const uint32_t b_ld = (uint32_t)(wn * 32 + ((bsel >> 1) * 8) + (lane & 7)) * STRIDE
                        + (bsel & 1) * 16;

    int cur_tile = g0 >> 9;
    for (int ii = 0; ii < WPC; ii++) {
        const int g = g0 + ii;
        const int st_idx = ii % NSTAGE;

        if (ii + 1 < WPC) {
            asm volatile("cp.async.wait_group 1;" ::: "memory");
        } else {
            asm volatile("cp.async.wait_group 0;" ::: "memory");
        }
        __syncthreads();   // all reads of stage (ii-1) retired; stage st_idx ready

        if (ii + 2 < WPC) issue(g0 + ii + 2, (ii + 2) % NSTAGE);

        if ((g >> 9) != cur_tile) {          // tile boundary: flush first segment
            flushacc(slotof(bid, cur_tile));
            cur_tile = g >> 9;
        }

        const uint32_t st = sb + st_idx * STAGE;
#pragma unroll
        for (int ks = 0; ks < 4; ks++) {
            const uint32_t ko = ks * 32;
            uint32_t af[4][4];
#pragma unroll
            for (int i = 0; i < 4; i++)
                ldm_x4(st + a_ld + (uint32_t)i * 16 * STRIDE + ko,
                       af[i][0], af[i][1], af[i][2], af[i][3]);
            uint32_t bf[2][4];
#pragma unroll
            for (int p = 0; p < 2; p++)
                ldm_x4(st + TILE_SM + b_ld + (uint32_t)p * 16 * STRIDE + ko,
                       bf[p][0], bf[p][1], bf[p][2], bf[p][3]);
#pragma unroll
            for (int i = 0; i < 4; i++)
#pragma unroll
                for (int j = 0; j < 4; j++) {
                    const int p = j >> 1, h = (j & 1) * 2;
                    mma16816(acc[i][j][0], acc[i][j][1], acc[i][j][2], acc[i][j][3],
                             af[i][0], af[i][1], af[i][2], af[i][3],
                             bf[p][h], bf[p][h + 1]);
                }
        }
    }

    flushacc(slotof(bid, cur_tile));
}

// ---------------------------------------------------------------------------
// Kernel 3: assemble G from static slot regions (deterministic, batched).
// Quadrants: (lo,lo)<-tile0, (lo,hi)<-tile1, (hi,hi)<-tile2,
// (hi,lo)<-tile1 transposed. UNCONDITIONAL 4-way-batched slot loop (MLP).
// Extracts diag -> g_sq; resets g_count.
// ---------------------------------------------------------------------------
__global__ __launch_bounds__(256) void reduce_kernel() {
    const int bi = blockIdx.x >> 3;
    const int bj = blockIdx.x & 7;
    const int t  = threadIdx.x;
    const int r  = t >> 3;
    const int c4 = (t & 7) * 4;

    const int qi = bi >> 2, qj = bj >> 2;
    const int twant = (qi == 0) ? ((qj == 0) ? 0 : 1) : ((qj == 1) ? 2 : 1);
    const bool trans = (qi == 1 && qj == 0);

    int sr, sc;
    if (!trans) { sr = (bi & 3) * 32 + r; sc = (bj & 3) * 32 + c4; }
    else        { sr = (bj & 3) * 32 + r; sc = (bi & 3) * 32 + c4; }

    const int sbase  = (twant == 0) ? 0 : (twant == 1) ? 43 : 87;
    const int nslots = (twant == 1) ? 44 : 43;
    const float* bp = g_part + (size_t)sbase * TILE_ELEMS + sr * 128 + sc;

    float4 A0 = make_float4(0.f,0.f,0.f,0.f), A1 = A0, A2 = A0, A3 = A0;
    int s = 0;
    for (; s + 4 <= nslots; s += 4) {
        float4 v0 = *reinterpret_cast<const float4*>(bp + (size_t)(s + 0) * TILE_ELEMS);
        float4 v1 = *reinterpret_cast<const float4*>(bp + (size_t)(s + 1) * TILE_ELEMS);
        float4 v2 = *reinterpret_cast<const float4*>(bp + (size_t)(s + 2) * TILE_ELEMS);
        float4 v3 = *reinterpret_cast<const float4*>(bp + (size_t)(s + 3) * TILE_ELEMS);
        A0.x += v0.x; A0.y += v0.y; A0.z += v0.z; A0.w += v0.w;
        A1.x += v1.x; A1.y += v1.y; A1.z += v1.z; A1.w += v1.w;
        A2.x += v2.x; A2.y += v2.y; A2.z += v2.z; A2.w += v2.w;
        A3.x += v3.x; A3.y += v3.y; A3.z += v3.z; A3.w += v3.w;
    }
    for (; s < nslots; s++) {
        float4 v = *reinterpret_cast<const float4*>(bp + (size_t)s * TILE_ELEMS);
        A0.x += v.x; A0.y += v.y; A0.z += v.z; A0.w += v.w;
    }
    float4 acc;
    acc.x = (A0.x + A1.x) + (A2.x + A3.x);
    acc.y = (A0.y + A1.y) + (A2.y + A3.y);
    acc.z = (A0.z + A1.z) + (A2.z + A3.z);
    acc.w = (A0.w + A1.w) + (A2.w + A3.w);

    float4 gv;
    __shared__ float s2[32][33];
    if (!trans) {
        gv = acc;
    } else {
        s2[r][c4 + 0] = acc.x; s2[r][c4 + 1] = acc.y;
        s2[r][c4 + 2] = acc.z; s2[r][c4 + 3] = acc.w;
        __syncthreads();
        gv.x = s2[c4 + 0][r]; gv.y = s2[c4 + 1][r];
        gv.z = s2[c4 + 2][r]; gv.w = s2[c4 + 3][r];
    }

    const int grow = bi * 32 + r;
    const int gcol = bj * 32 + c4;
    *reinterpret_cast<float4*>(g_G + grow * BB + gcol) = gv;

    if (grow >= gcol && grow < gcol + 4) {   // diag element lives in this unit
        const int d = grow - gcol;
        g_sq[grow] = (d == 0) ? gv.x : (d == 1) ? gv.y : (d == 2) ? gv.z : gv.w;
    }
    if (blockIdx.x == 0 && t == 0) g_count = 0;
}

// ---------------------------------------------------------------------------
// Kernel 4: loss, block-per-anchor (grid=256) impostor-major -- R7 verbatim.
// loss(a) = sum_{k imp} sum_{b pos} relu((D_ab+m) - D_ak); cnt = nPos*nImp.
// Positives compacted via ballot prefix-scan, padded with -1e30 (self-mask).
// Fused final reduction via last-block election (deterministic tree).
// ---------------------------------------------------------------------------
__global__ __launch_bounds__(256) void loss_kernel(const int* __restrict__ mods,
                                                   float* __restrict__ out) {
    const int a = blockIdx.x;
    const int t = threadIdx.x;
    const int w = t >> 5;
    const int lane = t & 31;
    __shared__ int    smod[BB];
    __shared__ float  pv[BB + 8];
    __shared__ int    wpos[8], wimp[8];
    __shared__ double dacc[BB];
    __shared__ int    is_last;

    smod[t] = mods[t];
    __syncthreads();

    const int ma = smod[a];
    const float sqa = g_sq[a];
    const float sqt = g_sq[t];
    float d2 = sqa + sqt - 2.f * g_G[a * BB + t];
    d2 = fmaxf(d2, 0.f);
    const float dv = (d2 > 0.f) ? sqrtf(d2) : 0.f;

    const bool imp = (smod[t] != ma);
    const bool pos = (t != a) && !imp;

    const uint32_t bp = __ballot_sync(0xFFFFFFFFu, pos);
    const uint32_t bi = __ballot_sync(0xFFFFFFFFu, imp);
    if (lane == 0) { wpos[w] = __popc(bp); wimp[w] = __popc(bi); }
    __syncthreads();

    int base = 0, nPos = 0, nImp = 0;
#pragma unroll
    for (int i = 0; i < 8; i++) {
        if (i < w) base += wpos[i];
        nPos += wpos[i];
        nImp += wimp[i];
    }
    if (pos) pv[base + __popc(bp & ((1u << lane) - 1u))] = dv + MARGIN;
    if (t < 8) pv[nPos + t] = -1e30f;   // padding: relu self-masks
    __syncthreads();

    float a0 = 0.f, a1 = 0.f;
    if (imp) {
        const float dak = dv;
        const int n8 = (nPos + 7) & ~7;
#pragma unroll 1
        for (int i = 0; i < n8; i += 8) {
            a0 += fmaxf(pv[i + 0] - dak, 0.f);
            a1 += fmaxf(pv[i + 1] - dak, 0.f);
            a0 += fmaxf(pv[i + 2] - dak, 0.f);
            a1 += fmaxf(pv[i + 3] - dak, 0.f);
            a0 += fmaxf(pv[i + 4] - dak, 0.f);
            a1 += fmaxf(pv[i + 5] - dak, 0.f);
            a0 += fmaxf(pv[i + 6] - dak, 0.f);
            a1 += fmaxf(pv[i + 7] - dak, 0.f);
        }
    }
    dacc[t] = (double)(a0 + a1);
    __syncthreads();
    for (int stride = 128; stride > 0; stride >>= 1) {
        if (t < stride) dacc[t] += dacc[t + stride];
        __syncthreads();
    }
    if (t == 0) {
        g_lossp[a] = dacc[0];
        g_cntp[a]  = (double)nPos * (double)nImp;
    }

    __threadfence();
    if (t == 0) {
        int old = atomicAdd(&g_count, 1);
        is_last = (old == BB - 1);
    }
    __syncthreads();
    if (is_last) {
        __threadfence();
        __shared__ double scnt2[BB];
        dacc[t]  = g_lossp[t];
        scnt2[t] = g_cntp[t];
        __syncthreads();
        for (int stride = 128; stride > 0; stride >>= 1) {
            if (t < stride) { dacc[t] += dacc[t + stride]; scnt2[t] += scnt2[t + stride]; }
            __syncthreads();
        }
        if (t == 0) out[0] = (float)(dacc[0] / scnt2[0]);
    }
}

// ---------------------------------------------------------------------------
extern "C" void kernel_launch(void* const* d_in, const int* in_sizes, int n_in,
                              void* d_out, int out_size) {
    const float* X    = (const float*)d_in[0];
    const int*   mods = (const int*)  d_in[1];
    (void)in_sizes; (void)n_in; (void)out_size;

    cudaFuncSetAttribute(gemm_kernel, cudaFuncAttributeMaxDynamicSharedMemorySize, SMEM_TOTAL);

    convert_kernel<<<(BB * DIM / 8) / 256, 256>>>(X);
    gemm_kernel<<<NCTA, 256, SMEM_TOTAL>>>();
    reduce_kernel<<<64, 256>>>();
    loss_kernel<<<BB, 256>>>(mods, (float*)d_out);
}